// round 8
// baseline (speedup 1.0000x reference)
#include <cuda_runtime.h>
#include <cstdint>
#include <cstddef>

#define RES_C     128
#define BATCH     4
#define T_START   8192
#define NBLK      40
#define SKIP_SIZE 4096

#define TN        64
#define NTHREADS  128            // 4 fat warps, 2 CTAs/SM

#define XPCH      128            // X/G row pitch (floats)

// smem regions (float offsets)
#define REGA      0              // X_a (32KB) -> stage-2 pair buf (even)
#define REGB      8192           // X_b (32KB) -> stage-2 pair buf (odd)
#define REGW      16384          // 3 x 16KB stage-1 weight bufs -> G (32KB)
#define SMEM_FLOATS 28672
#define SMEM_BYTES  (SMEM_FLOATS * 4)    // 114688 (112KB)

#define W1CHUNK   4096           // 16KB stage-1 chunk ([128o][32k])
#define W2PAIR    8192           // 32KB stage-2 pair  ([res 128x32][skip 128x32])
#define WBLK_FLOATS 32768        // per block per stage-group

static const int H_DIL[NBLK] = {
    1,2,4,8,16,32,64,128,256,512,
    1,2,4,8,16,32,64,128,256,512,
    1,2,4,8,16,32,64,128,256,512,
    1,2,4,8,16,32,64,128,256,512};

// ---------------- device scratch ----------------
__device__ float g_bufA[BATCH * RES_C * T_START];
__device__ float g_bufB[BATCH * RES_C * T_START];
__device__ float g_w1[NBLK * WBLK_FLOATS];   // 8 chunks [o128][k32] packed+swizzled
__device__ float g_w2[NBLK * WBLK_FLOATS];   // 4 pairs: [res 128x32 | skip 128x32]

// ---------------- layout helpers ----------------
__host__ __device__ __forceinline__ int packc(int k) {
    return ((k >> 4) << 4) | ((k & 3) << 2) | ((k & 15) >> 2);
}
__host__ __device__ __forceinline__ int fsw(int r) {
    return ((r & 1) << 4) | ((r & 6) << 1);
}

__device__ __forceinline__ uint32_t tf32u(float x) {
    uint32_t u;
    asm("cvt.rna.tf32.f32 %0, %1;" : "=r"(u) : "f"(x));
    return u;
}
__device__ __forceinline__ float tf32f(float x) { return __uint_as_float(tf32u(x)); }

__device__ __forceinline__ void mma8(float c[4], uint32_t a0, uint32_t a1, uint32_t a2,
                                     uint32_t a3, uint32_t b0, uint32_t b1) {
    asm volatile(
        "mma.sync.aligned.m16n8k8.row.col.f32.tf32.tf32.f32 "
        "{%0,%1,%2,%3}, {%4,%5,%6,%7}, {%8,%9}, {%0,%1,%2,%3};\n"
        : "+f"(c[0]), "+f"(c[1]), "+f"(c[2]), "+f"(c[3])
        : "r"(a0), "r"(a1), "r"(a2), "r"(a3), "r"(b0), "r"(b1));
}

__device__ __forceinline__ void lds128(uint32_t r[4], uint32_t addr) {
    asm volatile("ld.shared.v4.b32 {%0,%1,%2,%3}, [%4];"
                 : "=r"(r[0]), "=r"(r[1]), "=r"(r[2]), "=r"(r[3]) : "r"(addr));
}

__device__ __forceinline__ float gate_fn(float y) {
    float u = __expf(-fabsf(y));
    float a = (1.f - u) * __frcp_rn(1.f + u * u);
    return (y >= 0.f) ? a : -u * a;
}

#define CPWAIT(n) asm volatile("cp.async.wait_group " #n ";\n")

// ---------------- weight prep (identical layouts to round 6) ----------------
__global__ void prep_w1(const float* __restrict__ w, float* __restrict__ out, int n) {
    int i = blockIdx.x * blockDim.x + threadIdx.x;
    if (i >= n) return;
    int kl  = i & 31;
    int o   = (i >> 5) & 127;
    int ch  = (i >> 12) & 7;
    int blk = i >> 15;
    int kg  = ch * 32 + kl;
    float v = (kg < 128) ? w[(((blk * 128 + o) * 128) + kg) * 2 + 0]
                         : w[(((blk * 128 + o) * 128) + (kg - 128)) * 2 + 1];
    out[(size_t)blk * WBLK_FLOATS + ch * W1CHUNK + o * 32 + (packc(kl) ^ fsw(o))] = tf32f(v);
}
__global__ void prep_w2(const float* __restrict__ wr, const float* __restrict__ ws,
                        float* __restrict__ out, int n) {
    int i = blockIdx.x * blockDim.x + threadIdx.x;
    if (i >= n) return;
    int kl  = i & 31;
    int o   = (i >> 5) & 127;
    int h   = (i >> 12) & 1;
    int pr  = (i >> 13) & 3;
    int blk = i >> 15;
    float v = (h == 0) ? wr[((blk * 128 + o) * 128) + pr * 32 + kl]
                       : ws[((blk * 128 + o) * 128) + pr * 32 + kl];
    out[(size_t)blk * WBLK_FLOATS + pr * W2PAIR + h * 4096 + o * 32 + (packc(kl) ^ fsw(o))]
        = tf32f(v);
}

// ---------------- fused per-block kernel ----------------
__global__ __launch_bounds__(NTHREADS, 2)
void wavenet_block(const float* __restrict__ xin, float* __restrict__ xout,
                   float* __restrict__ skip,
                   const float* __restrict__ w1g, const float* __restrict__ w2g,
                   const float* __restrict__ brs, const float* __restrict__ bsk,
                   int Tc, int d, int L, int sstart)
{
    extern __shared__ float sm[];
    const uint32_t sb = (uint32_t)__cvta_generic_to_shared(sm);

    const int tid  = threadIdx.x;
    const int lane = tid & 31;
    const int wid  = tid >> 5;        // 0..3
    const int g    = lane >> 2;
    const int tg   = lane & 3;
    const int tg4  = tg << 2;
    const int fg   = fsw(g);
    const int t0   = blockIdx.x * TN;
    const int b    = blockIdx.y;

    const int wm = (wid & 1) * 32;    // time tile (M32)
    const int wn = (wid >> 1) * 64;   // out tile (N64, nt=8)

    const bool full      = (t0 + TN <= L);
    const bool need_skip = (t0 + TN > sstart);

    // ---- stage-1 weight chunk fetch (16KB into W rotation) ----
    auto fetch1 = [&](int c) {
        const float* src = w1g + c * W1CHUNK;
        uint32_t dst = sb + (REGW + (c % 3) * W1CHUNK) * 4;
        #pragma unroll
        for (int i = 0; i < 8; ++i) {
            int e = tid + i * NTHREADS;
            asm volatile("cp.async.cg.shared.global [%0], [%1], 16;\n"
                         :: "r"(dst + e * 16), "l"(src + e * 4));
        }
        asm volatile("cp.async.commit_group;\n");
    };
    // ---- stage-2 pair fetch (32KB into region A or B) ----
    auto fetch2 = [&](int p, int region) {
        const float* src = w2g + p * W2PAIR;
        uint32_t dst = sb + region * 4;
        #pragma unroll
        for (int i = 0; i < 16; ++i) {
            int e = tid + i * NTHREADS;
            asm volatile("cp.async.cg.shared.global [%0], [%1], 16;\n"
                         :: "r"(dst + e * 16), "l"(src + e * 4));
        }
        asm volatile("cp.async.commit_group;\n");
    };

    fetch1(0);
    fetch1(1);

    // ---- X tile load: X_a (regA) k 0..127 <- x[k][tt]; X_b (regB) k 0..127 <- x[k][tt+d]
    const float* xb = xin + (size_t)b * RES_C * Tc;
    {
        const int t    = tid & 63;
        const int half = tid >> 6;            // 0 -> X_a, 1 -> X_b
        const int tt   = t0 + t;
        const int ft   = fsw(t);
        const uint32_t xrow = sb + ((half ? REGB : REGA) + t * XPCH) * 4;
        const float* base = xb + (half ? d : 0);
        const bool ok_t = half ? (tt < L) : (tt < Tc);
        if (full) {
            #pragma unroll
            for (int idx = 0; idx < 32; ++idx) {
                const int kb    = (idx >> 2) * 16 + (idx & 3);
                const int cbase = (idx >> 2) * 16 + (idx & 3) * 4;
                uint32_t u[4];
                #pragma unroll
                for (int j = 0; j < 4; ++j)
                    u[j] = tf32u(base[(size_t)(kb + 4 * j) * Tc + tt]);
                asm volatile("st.shared.v4.b32 [%0], {%1,%2,%3,%4};"
                             :: "r"(xrow + (uint32_t)((cbase ^ ft) << 2)),
                                "r"(u[0]), "r"(u[1]), "r"(u[2]), "r"(u[3]));
            }
        } else {
            #pragma unroll
            for (int idx = 0; idx < 32; ++idx) {
                const int kb    = (idx >> 2) * 16 + (idx & 3);
                const int cbase = (idx >> 2) * 16 + (idx & 3) * 4;
                uint32_t u[4];
                #pragma unroll
                for (int j = 0; j < 4; ++j) {
                    float v = ok_t ? base[(size_t)(kb + 4 * j) * Tc + tt] : 0.f;
                    u[j] = tf32u(v);
                }
                asm volatile("st.shared.v4.b32 [%0], {%1,%2,%3,%4};"
                             :: "r"(xrow + (uint32_t)((cbase ^ ft) << 2)),
                                "r"(u[0]), "r"(u[1]), "r"(u[2]), "r"(u[3]));
            }
        }
    }

    uint32_t aRowA[2], aRowB[2], gRow[2];
    #pragma unroll
    for (int mt = 0; mt < 2; ++mt) {
        const int r = wm + mt * 16 + g;
        aRowA[mt] = sb + (REGA + r * XPCH) * 4;
        aRowB[mt] = sb + (REGB + r * XPCH) * 4;
        gRow[mt]  = sb + (REGW + r * XPCH) * 4;
    }

    float acc1[2][8][4];
    #pragma unroll
    for (int i = 0; i < 2; ++i)
        #pragma unroll
        for (int j = 0; j < 8; ++j)
            #pragma unroll
            for (int q = 0; q < 4; ++q) acc1[i][j][q] = 0.f;

    // one stage-1 compute phase: chunk c, A from aRow (+8*pitch), k-cols kb..kb+31
    auto s1_phase = [&](int c, const uint32_t aRow[2], int kb) {
        const uint32_t wbuf = sb + (REGW + (c % 3) * W1CHUNK) * 4;
        #pragma unroll
        for (int P = 0; P < 2; ++P) {
            const int col  = ((kb + P * 16 + tg4) ^ fg) << 2;
            const int colw = ((P * 16 + tg4) ^ fg) << 2;
            uint32_t A0[2][4], A1[2][4], Bf[8][4];
            #pragma unroll
            for (int mt = 0; mt < 2; ++mt) {
                lds128(A0[mt], aRow[mt] + col);
                lds128(A1[mt], aRow[mt] + 8 * XPCH * 4 + col);
            }
            #pragma unroll
            for (int nt = 0; nt < 8; ++nt)
                lds128(Bf[nt], wbuf + (uint32_t)(wn + nt * 8 + g) * (32 * 4) + colw);
            #pragma unroll
            for (int mt = 0; mt < 2; ++mt)
                #pragma unroll
                for (int nt = 0; nt < 8; ++nt) {
                    mma8(acc1[mt][nt], A0[mt][0], A1[mt][0], A0[mt][1], A1[mt][1],
                         Bf[nt][0], Bf[nt][1]);
                    mma8(acc1[mt][nt], A0[mt][2], A1[mt][2], A0[mt][3], A1[mt][3],
                         Bf[nt][2], Bf[nt][3]);
                }
        }
    };

    // ===== stage 1, first half: chunks 0-3 on X_a =====
    #pragma unroll 1
    for (int p = 0; p < 4; ++p) {
        CPWAIT(1);
        __syncthreads();
        fetch1(p + 2);                 // c2..c5
        s1_phase(p, aRowA, p * 32);
    }
    // ===== stage 1, second half: chunks 4-7 on X_b; inject pair-0 prefetch into regA =====
    {
        CPWAIT(1);                     // ensures c4
        __syncthreads();               // regA reads finished
        fetch1(6);
        fetch2(0, REGA);               // long-range prefetch of stage-2 pair 0
        s1_phase(4, aRowB, 0);
        CPWAIT(2);                     // ensures c5
        __syncthreads();
        fetch1(7);
        s1_phase(5, aRowB, 32);
        CPWAIT(2);                     // ensures c6
        __syncthreads();
        s1_phase(6, aRowB, 64);
        CPWAIT(0);                     // c7 + P0 done
        __syncthreads();
        s1_phase(7, aRowB, 96);
    }

    // ---- pair-1 prefetch into regB (free now), then gate into G (W region) ----
    __syncthreads();                   // all stage-1 reads of regB / W complete
    fetch2(1, REGB);
    #pragma unroll
    for (int mt = 0; mt < 2; ++mt)
        #pragma unroll
        for (int nt = 0; nt < 8; ++nt) {
            const int t = wm + mt * 16 + g;
            const int o = wn + nt * 8 + 2 * tg;
            const int c0 = packc(o)     ^ fsw(t);
            const int c1 = packc(o + 1) ^ fsw(t);
            float* cc = acc1[mt][nt];
            sm[REGW + t * XPCH + c0]       = tf32f(gate_fn(cc[0]));
            sm[REGW + t * XPCH + c1]       = tf32f(gate_fn(cc[1]));
            sm[REGW + (t + 8) * XPCH + c0] = tf32f(gate_fn(cc[2]));
            sm[REGW + (t + 8) * XPCH + c1] = tf32f(gate_fn(cc[3]));
        }
    __syncthreads();                   // publish G; P0 visible

    // ===== stage 2: 4 merged phases (res + skip share G fragments) =====
    float acc2[2][8][4], acc3[2][8][4];
    #pragma unroll
    for (int i = 0; i < 2; ++i)
        #pragma unroll
        for (int j = 0; j < 8; ++j)
            #pragma unroll
            for (int q = 0; q < 4; ++q) { acc2[i][j][q] = 0.f; acc3[i][j][q] = 0.f; }

    #pragma unroll 1
    for (int s = 0; s < 4; ++s) {
        if (s > 0) {
            CPWAIT(0);
            __syncthreads();
            if (s == 1) fetch2(2, REGA);
            if (s == 2) fetch2(3, REGB);
        }
        const uint32_t pbuf = sb + ((s & 1) ? REGB : REGA) * 4;
        const int kb = s * 32;
        #pragma unroll
        for (int P = 0; P < 2; ++P) {
            const int col  = ((kb + P * 16 + tg4) ^ fg) << 2;
            const int colw = ((P * 16 + tg4) ^ fg) << 2;
            uint32_t A0[2][4], A1[2][4], Bf[8][4];
            #pragma unroll
            for (int mt = 0; mt < 2; ++mt) {
                lds128(A0[mt], gRow[mt] + col);
                lds128(A1[mt], gRow[mt] + 8 * XPCH * 4 + col);
            }
            #pragma unroll
            for (int nt = 0; nt < 8; ++nt)
                lds128(Bf[nt], pbuf + (uint32_t)(wn + nt * 8 + g) * (32 * 4) + colw);
            #pragma unroll
            for (int mt = 0; mt < 2; ++mt)
                #pragma unroll
                for (int nt = 0; nt < 8; ++nt) {
                    mma8(acc2[mt][nt], A0[mt][0], A1[mt][0], A0[mt][1], A1[mt][1],
                         Bf[nt][0], Bf[nt][1]);
                    mma8(acc2[mt][nt], A0[mt][2], A1[mt][2], A0[mt][3], A1[mt][3],
                         Bf[nt][2], Bf[nt][3]);
                }
            if (need_skip) {
                #pragma unroll
                for (int nt = 0; nt < 8; ++nt)
                    lds128(Bf[nt], pbuf + 4096 * 4 + (uint32_t)(wn + nt * 8 + g) * (32 * 4) + colw);
                #pragma unroll
                for (int mt = 0; mt < 2; ++mt)
                    #pragma unroll
                    for (int nt = 0; nt < 8; ++nt) {
                        mma8(acc3[mt][nt], A0[mt][0], A1[mt][0], A0[mt][1], A1[mt][1],
                             Bf[nt][0], Bf[nt][1]);
                        mma8(acc3[mt][nt], A0[mt][2], A1[mt][2], A0[mt][3], A1[mt][3],
                             Bf[nt][2], Bf[nt][3]);
                    }
            }
        }
    }

    // ---- res epilogue: direct STG from accumulators ----
    #pragma unroll
    for (int mt = 0; mt < 2; ++mt)
        #pragma unroll
        for (int nt = 0; nt < 8; ++nt) {
            const int t = wm + mt * 16 + g;
            const int o = wn + nt * 8 + 2 * tg;
            const float b0 = __ldg(brs + o);
            const float b1 = __ldg(brs + o + 1);
            const size_t r0 = (size_t)(b * 128 + o) * L;
            const size_t x0 = (size_t)o * Tc;
            float* cc = acc2[mt][nt];
            if (full) {
                xout[r0 + t0 + t]         = cc[0] + b0 + xb[x0 + t0 + t + d];
                xout[r0 + L + t0 + t]     = cc[1] + b1 + xb[x0 + Tc + t0 + t + d];
                xout[r0 + t0 + t + 8]     = cc[2] + b0 + xb[x0 + t0 + t + 8 + d];
                xout[r0 + L + t0 + t + 8] = cc[3] + b1 + xb[x0 + Tc + t0 + t + 8 + d];
            } else {
                if (t0 + t < L) {
                    xout[r0 + t0 + t]     = cc[0] + b0 + xb[x0 + t0 + t + d];
                    xout[r0 + L + t0 + t] = cc[1] + b1 + xb[x0 + Tc + t0 + t + d];
                }
                if (t0 + t + 8 < L) {
                    xout[r0 + t0 + t + 8]     = cc[2] + b0 + xb[x0 + t0 + t + 8 + d];
                    xout[r0 + L + t0 + t + 8] = cc[3] + b1 + xb[x0 + Tc + t0 + t + 8 + d];
                }
            }
        }

    // ---- skip epilogue ----
    if (need_skip) {
        const bool wfull = full && (t0 >= sstart);
        #pragma unroll
        for (int mt = 0; mt < 2; ++mt)
            #pragma unroll
            for (int nt = 0; nt < 8; ++nt) {
                const int t = wm + mt * 16 + g;
                const int o = wn + nt * 8 + 2 * tg;
                const float b0 = __ldg(bsk + o);
                const float b1 = __ldg(bsk + o + 1);
                const size_t r0 = (size_t)(b * 128 + o) * SKIP_SIZE - sstart;
                float* cc = acc3[mt][nt];
                if (wfull) {
                    skip[r0 + t0 + t]                 = cc[0] + b0;
                    skip[r0 + SKIP_SIZE + t0 + t]     = cc[1] + b1;
                    skip[r0 + t0 + t + 8]             = cc[2] + b0;
                    skip[r0 + SKIP_SIZE + t0 + t + 8] = cc[3] + b1;
                } else {
                    const int tt0 = t0 + t, tt1 = t0 + t + 8;
                    if (tt0 >= sstart && tt0 < L) {
                        skip[r0 + tt0]             = cc[0] + b0;
                        skip[r0 + SKIP_SIZE + tt0] = cc[1] + b1;
                    }
                    if (tt1 >= sstart && tt1 < L) {
                        skip[r0 + tt1]             = cc[2] + b0;
                        skip[r0 + SKIP_SIZE + tt1] = cc[3] + b1;
                    }
                }
            }
    }

    CPWAIT(0);   // drain before CTA exit
}

// ---------------- host launcher ----------------
extern "C" void kernel_launch(void* const* d_in, const int* in_sizes, int n_in,
                              void* d_out, int out_size) {
    (void)in_sizes; (void)n_in; (void)out_size;

    const float* x     = (const float*)d_in[0];
    const float* wdil  = (const float*)d_in[1];
    const float* wres  = (const float*)d_in[2];
    const float* bres  = (const float*)d_in[3];
    const float* wskip = (const float*)d_in[4];
    const float* bskip = (const float*)d_in[5];
    float* out = (float*)d_out;

    float *bufA, *bufB, *w1, *w2;
    cudaGetSymbolAddress((void**)&bufA, g_bufA);
    cudaGetSymbolAddress((void**)&bufB, g_bufB);
    cudaGetSymbolAddress((void**)&w1,   g_w1);
    cudaGetSymbolAddress((void**)&w2,   g_w2);

    cudaFuncSetAttribute(wavenet_block, cudaFuncAttributeMaxDynamicSharedMemorySize, SMEM_BYTES);

    const int n1 = NBLK * WBLK_FLOATS;
    prep_w1<<<(n1 + 255) / 256, 256>>>(wdil, w1, n1);
    prep_w2<<<(n1 + 255) / 256, 256>>>(wres, wskip, w2, n1);

    int Tc = T_START;
    const float* cur = x;
    float* nxt = bufA;
    for (int blk = 0; blk < NBLK; ++blk) {
        const int d = H_DIL[blk];
        const int L = Tc - d;
        dim3 grid((L + TN - 1) / TN, BATCH);
        wavenet_block<<<grid, NTHREADS, SMEM_BYTES>>>(
            cur, nxt,
            out + (size_t)blk * BATCH * RES_C * SKIP_SIZE,
            w1 + (size_t)blk * WBLK_FLOATS,
            w2 + (size_t)blk * WBLK_FLOATS,
            bres + blk * 128, bskip + blk * 128,
            Tc, d, L, L - SKIP_SIZE);
        cur = nxt;
        nxt = (nxt == bufA) ? bufB : bufA;
        Tc = L;
    }
}

// round 9
// speedup vs baseline: 1.4513x; 1.4513x over previous
#include <cuda_runtime.h>
#include <cuda_fp16.h>
#include <cstdint>
#include <cstddef>

#define RES_C     128
#define BATCH     4
#define T_START   8192
#define NBLK      40
#define SKIP_SIZE 4096

#define TN        64
#define NTHREADS  256            // 8 warps, 2 CTAs/SM

// smem byte offsets
#define REGA_B    0              // X_a (16KB) -> stage-2 pair buf (even)
#define REGB_B    16384          // X_b (16KB) -> stage-2 pair buf (odd)
#define REGW_B    32768          // 3 x 8KB stage-1 weight chunks
#define REGG_B    57344          // G (16KB)
#define SMEM_BYTES 73728         // 72KB -> 2 CTAs/SM (smem) ; regs cap 128

#define W1CHUNK_H 4096           // halves per stage-1 chunk (8KB): [128 o][32 k packed]
#define W2PAIR_H  8192           // halves per stage-2 pair (16KB): [res 128x32][skip 128x32]
#define W1BLK_H   32768
#define W2BLK_H   32768

static const int H_DIL[NBLK] = {
    1,2,4,8,16,32,64,128,256,512,
    1,2,4,8,16,32,64,128,256,512,
    1,2,4,8,16,32,64,128,256,512,
    1,2,4,8,16,32,64,128,256,512};

// ---------------- device scratch ----------------
__device__ float g_bufA[BATCH * RES_C * T_START];
__device__ float g_bufB[BATCH * RES_C * T_START];
__device__ __align__(16) __half g_w1h[NBLK * W1BLK_H];
__device__ __align__(16) __half g_w2h[NBLK * W2BLK_H];

// ---------------- layout helpers ----------------
// fp16 packing within a 32-k block: k = 2*tg + 8*j + e  ->  half pos = tg*8 + j*2 + e
__host__ __device__ __forceinline__ int hpos(int kl) {
    return ((kl >> 1) & 3) * 8 + ((kl >> 3) & 3) * 2 + (kl & 1);
}
// per-row 3-bit granule swizzle (16B granules)
__host__ __device__ __forceinline__ int sxr(int r) {
    return ((r & 1) << 2) | ((r >> 1) & 3);
}

__device__ __forceinline__ void mma16(float c[4], uint32_t a0, uint32_t a1, uint32_t a2,
                                      uint32_t a3, uint32_t b0, uint32_t b1) {
    asm volatile(
        "mma.sync.aligned.m16n8k16.row.col.f32.f16.f16.f32 "
        "{%0,%1,%2,%3}, {%4,%5,%6,%7}, {%8,%9}, {%0,%1,%2,%3};\n"
        : "+f"(c[0]), "+f"(c[1]), "+f"(c[2]), "+f"(c[3])
        : "r"(a0), "r"(a1), "r"(a2), "r"(a3), "r"(b0), "r"(b1));
}

__device__ __forceinline__ void lds128(uint32_t r[4], uint32_t addr) {
    asm volatile("ld.shared.v4.b32 {%0,%1,%2,%3}, [%4];"
                 : "=r"(r[0]), "=r"(r[1]), "=r"(r[2]), "=r"(r[3]) : "r"(addr));
}

__device__ __forceinline__ float gate_fn(float y) {
    float u = __expf(-fabsf(y));
    float a = (1.f - u) * __frcp_rn(1.f + u * u);
    return (y >= 0.f) ? a : -u * a;
}

__device__ __forceinline__ uint32_t h2u(__half2 h) {
    return *reinterpret_cast<uint32_t*>(&h);
}

#define CPWAIT(n) asm volatile("cp.async.wait_group " #n ";\n")

// ---------------- weight prep (fp16, packed) ----------------
__global__ void prep_w1(const float* __restrict__ w, __half* __restrict__ out, int n) {
    int i = blockIdx.x * blockDim.x + threadIdx.x;
    if (i >= n) return;
    int kl  = i & 31;
    int o   = (i >> 5) & 127;
    int ch  = (i >> 12) & 7;
    int blk = i >> 15;
    int kg  = ch * 32 + kl;
    float v = (kg < 128) ? w[(((blk * 128 + o) * 128) + kg) * 2 + 0]
                         : w[(((blk * 128 + o) * 128) + (kg - 128)) * 2 + 1];
    out[(size_t)blk * W1BLK_H + ch * W1CHUNK_H + o * 32 + hpos(kl)] = __float2half_rn(v);
}
__global__ void prep_w2(const float* __restrict__ wr, const float* __restrict__ ws,
                        __half* __restrict__ out, int n) {
    int i = blockIdx.x * blockDim.x + threadIdx.x;
    if (i >= n) return;
    int kl  = i & 31;
    int o   = (i >> 5) & 127;
    int h   = (i >> 12) & 1;
    int pr  = (i >> 13) & 3;
    int blk = i >> 15;
    float v = (h == 0) ? wr[((blk * 128 + o) * 128) + pr * 32 + kl]
                       : ws[((blk * 128 + o) * 128) + pr * 32 + kl];
    out[(size_t)blk * W2BLK_H + pr * W2PAIR_H + h * 4096 + o * 32 + hpos(kl)]
        = __float2half_rn(v);
}

// ---------------- fused per-block kernel (fp16 MMA) ----------------
__global__ __launch_bounds__(NTHREADS, 2)
void wavenet_block(const float* __restrict__ xin, float* __restrict__ xout,
                   float* __restrict__ skip,
                   const __half* __restrict__ w1g, const __half* __restrict__ w2g,
                   const float* __restrict__ brs, const float* __restrict__ bsk,
                   int Tc, int d, int L, int sstart)
{
    extern __shared__ char smc[];
    const uint32_t sb = (uint32_t)__cvta_generic_to_shared(smc);

    const int tid  = threadIdx.x;
    const int lane = tid & 31;
    const int wid  = tid >> 5;
    const int g    = lane >> 2;
    const int tg   = lane & 3;
    const int sg   = sxr(g);          // s(row) for all this thread's frag rows (rows ≡ g mod 8, +8 invariant)
    const int t0   = blockIdx.x * TN;
    const int b    = blockIdx.y;

    const int wm = (wid & 1) * 32;    // time tile (M32)
    const int wn = (wid >> 1) * 32;   // out tile (N32)

    const bool full      = (t0 + TN <= L);
    const bool need_skip = (t0 + TN > sstart);

    // granule offsets for A-side (X/G rows are 256B: 16 granules)
    uint32_t aof[4];
    #pragma unroll
    for (int kb = 0; kb < 4; ++kb)
        aof[kb] = (uint32_t)((((kb << 2) + tg) ^ sg) << 4);

    // ---- stage-1 weight chunk fetch (8KB into 3-slot REGW rotation) ----
    auto fetch1 = [&](int c) {
        const __half* src = w1g + c * W1CHUNK_H;
        uint32_t dst = sb + REGW_B + (uint32_t)(c % 3) * 8192;
        #pragma unroll
        for (int i = 0; i < 2; ++i) {
            int e = tid + i * NTHREADS;
            asm volatile("cp.async.cg.shared.global [%0], [%1], 16;\n"
                         :: "r"(dst + e * 16), "l"(src + e * 8));
        }
        asm volatile("cp.async.commit_group;\n");
    };
    // ---- stage-2 pair fetch (16KB into region A or B) ----
    auto fetch2 = [&](int p, uint32_t regByte) {
        const __half* src = w2g + p * W2PAIR_H;
        uint32_t dst = sb + regByte;
        #pragma unroll
        for (int i = 0; i < 4; ++i) {
            int e = tid + i * NTHREADS;
            asm volatile("cp.async.cg.shared.global [%0], [%1], 16;\n"
                         :: "r"(dst + e * 16), "l"(src + e * 8));
        }
        asm volatile("cp.async.commit_group;\n");
    };

    fetch1(0);
    fetch1(1);

    // ---- X tile load: X_a (k 0..127 of x[.][tt]) / X_b (x[.][tt+d]); fp16 packed+swizzled
    const float* xb = xin + (size_t)b * RES_C * Tc;
    {
        const int r    = tid & 63;
        const int quad = tid >> 6;          // 0..3
        const int reg  = quad >> 1;         // 0 -> X_a, 1 -> X_b
        const int kbb  = (quad & 1) << 1;   // kb base 0 or 2
        const int tt   = t0 + r;
        const int sgr  = sxr(r);
        const uint32_t rowb = sb + (reg ? REGB_B : REGA_B) + (uint32_t)r * 256;
        const float* bp = xb + (reg ? d : 0);
        const bool okt = reg ? (tt < L) : (tt < Tc);
        #pragma unroll
        for (int kb2 = 0; kb2 < 2; ++kb2)
            #pragma unroll
            for (int tg2 = 0; tg2 < 4; ++tg2) {
                const int kb = kbb + kb2;
                uint32_t v[4];
                #pragma unroll
                for (int j = 0; j < 4; ++j) {
                    const int k0 = kb * 32 + 2 * tg2 + 8 * j;
                    float f0 = 0.f, f1 = 0.f;
                    if (okt) {
                        f0 = bp[(size_t)k0 * Tc + tt];
                        f1 = bp[(size_t)(k0 + 1) * Tc + tt];
                    }
                    v[j] = h2u(__floats2half2_rn(f0, f1));
                }
                uint32_t sa = rowb + (uint32_t)(((((kb << 2) + tg2) ^ sgr)) << 4);
                asm volatile("st.shared.v4.b32 [%0], {%1,%2,%3,%4};"
                             :: "r"(sa), "r"(v[0]), "r"(v[1]), "r"(v[2]), "r"(v[3]));
            }
    }

    // A-row base addresses (rows are 256B in X regions and in G)
    const uint32_t aA0 = sb + REGA_B + (uint32_t)(wm + g) * 256;
    const uint32_t aA1 = aA0 + 16 * 256;
    const uint32_t aB0 = sb + REGB_B + (uint32_t)(wm + g) * 256;
    const uint32_t aB1 = aB0 + 16 * 256;
    const uint32_t gR0 = sb + REGG_B + (uint32_t)(wm + g) * 256;
    const uint32_t gR1 = gR0 + 16 * 256;

    float acc1[2][4][4];
    #pragma unroll
    for (int i = 0; i < 2; ++i)
        #pragma unroll
        for (int j = 0; j < 4; ++j)
            #pragma unroll
            for (int q = 0; q < 4; ++q) acc1[i][j][q] = 0.f;

    // one stage-1 phase: chunk c, A rows at (r0,r1) [+2048 = rows+8], k-block kb
    auto s1_phase = [&](int c, uint32_t r0, uint32_t r1, int kb) {
        const uint32_t wb = sb + REGW_B + (uint32_t)(c % 3) * 8192;
        const uint32_t ao = aof[kb];
        uint32_t A0[2][4], A1[2][4], Bf[4][4];
        lds128(A0[0], r0 + ao);
        lds128(A1[0], r0 + 2048 + ao);
        lds128(A0[1], r1 + ao);
        lds128(A1[1], r1 + 2048 + ao);
        #pragma unroll
        for (int nt = 0; nt < 4; ++nt)
            lds128(Bf[nt], wb + (uint32_t)(wn + nt * 8 + g) * 64 + tg * 16);
        #pragma unroll
        for (int mt = 0; mt < 2; ++mt)
            #pragma unroll
            for (int nt = 0; nt < 4; ++nt) {
                mma16(acc1[mt][nt], A0[mt][0], A1[mt][0], A0[mt][1], A1[mt][1],
                      Bf[nt][0], Bf[nt][1]);
                mma16(acc1[mt][nt], A0[mt][2], A1[mt][2], A0[mt][3], A1[mt][3],
                      Bf[nt][2], Bf[nt][3]);
            }
    };

    // ===== stage 1, first half: chunks 0-3 on X_a =====
    #pragma unroll 1
    for (int p = 0; p < 4; ++p) {
        CPWAIT(1);
        __syncthreads();
        fetch1(p + 2);
        s1_phase(p, aA0, aA1, p);
    }
    // ===== stage 1, second half: chunks 4-7 on X_b; pair-0 prefetch into regA =====
    {
        CPWAIT(1);                     // c4 ready
        __syncthreads();               // X_a reads done
        fetch1(6);
        fetch2(0, REGA_B);
        s1_phase(4, aB0, aB1, 0);
        CPWAIT(2);                     // c5 ready
        __syncthreads();
        fetch1(7);
        s1_phase(5, aB0, aB1, 1);
        CPWAIT(2);                     // c6 ready
        __syncthreads();
        s1_phase(6, aB0, aB1, 2);
        CPWAIT(0);                     // c7 + P0 done
        __syncthreads();
        s1_phase(7, aB0, aB1, 3);
    }

    // ---- pair-1 prefetch into regB (X_b dead), gate acc1 -> G (fp16 packed+swizzled) ----
    __syncthreads();                   // all stage-1 reads of regB complete
    fetch2(1, REGB_B);
    #pragma unroll
    for (int mt = 0; mt < 2; ++mt)
        #pragma unroll
        for (int nt = 0; nt < 4; ++nt) {
            const int t = wm + mt * 16 + g;
            const int o = wn + nt * 8 + 2 * tg;
            const int kbo = o >> 5, tgo = (o >> 1) & 3, jj = (o >> 3) & 3;
            const uint32_t ga = sb + REGG_B + (uint32_t)t * 256
                              + (uint32_t)(((((kbo << 2) + tgo) ^ sg)) << 4) + jj * 4;
            float* cc = acc1[mt][nt];
            uint32_t u0 = h2u(__floats2half2_rn(gate_fn(cc[0]), gate_fn(cc[1])));
            uint32_t u1 = h2u(__floats2half2_rn(gate_fn(cc[2]), gate_fn(cc[3])));
            asm volatile("st.shared.b32 [%0], %1;" :: "r"(ga), "r"(u0));
            asm volatile("st.shared.b32 [%0], %1;" :: "r"(ga + 2048), "r"(u1));
        }
    __syncthreads();                   // publish G; P0 visible

    // ===== stage 2: 4 merged phases (res + skip share G fragments) =====
    float acc2[2][4][4], acc3[2][4][4];
    #pragma unroll
    for (int i = 0; i < 2; ++i)
        #pragma unroll
        for (int j = 0; j < 4; ++j)
            #pragma unroll
            for (int q = 0; q < 4; ++q) { acc2[i][j][q] = 0.f; acc3[i][j][q] = 0.f; }

    #pragma unroll 1
    for (int s = 0; s < 4; ++s) {
        if (s > 0) {
            CPWAIT(0);
            __syncthreads();
            if (s == 1) fetch2(2, REGA_B);
            if (s == 2) fetch2(3, REGB_B);
        }
        const uint32_t pb = sb + ((s & 1) ? REGB_B : REGA_B);
        const uint32_t ao = aof[s];
        uint32_t A0[2][4], A1[2][4], Bf[4][4];
        lds128(A0[0], gR0 + ao);
        lds128(A1[0], gR0 + 2048 + ao);
        lds128(A0[1], gR1 + ao);
        lds128(A1[1], gR1 + 2048 + ao);
        #pragma unroll
        for (int nt = 0; nt < 4; ++nt)
            lds128(Bf[nt], pb + (uint32_t)(wn + nt * 8 + g) * 64 + tg * 16);
        #pragma unroll
        for (int mt = 0; mt < 2; ++mt)
            #pragma unroll
            for (int nt = 0; nt < 4; ++nt) {
                mma16(acc2[mt][nt], A0[mt][0], A1[mt][0], A0[mt][1], A1[mt][1],
                      Bf[nt][0], Bf[nt][1]);
                mma16(acc2[mt][nt], A0[mt][2], A1[mt][2], A0[mt][3], A1[mt][3],
                      Bf[nt][2], Bf[nt][3]);
            }
        if (need_skip) {
            #pragma unroll
            for (int nt = 0; nt < 4; ++nt)
                lds128(Bf[nt], pb + 8192 + (uint32_t)(wn + nt * 8 + g) * 64 + tg * 16);
            #pragma unroll
            for (int mt = 0; mt < 2; ++mt)
                #pragma unroll
                for (int nt = 0; nt < 4; ++nt) {
                    mma16(acc3[mt][nt], A0[mt][0], A1[mt][0], A0[mt][1], A1[mt][1],
                          Bf[nt][0], Bf[nt][1]);
                    mma16(acc3[mt][nt], A0[mt][2], A1[mt][2], A0[mt][3], A1[mt][3],
                          Bf[nt][2], Bf[nt][3]);
                }
        }
    }

    // ---- res epilogue: direct STG from accumulators ----
    #pragma unroll
    for (int mt = 0; mt < 2; ++mt)
        #pragma unroll
        for (int nt = 0; nt < 4; ++nt) {
            const int t = wm + mt * 16 + g;
            const int o = wn + nt * 8 + 2 * tg;
            const float b0 = __ldg(brs + o);
            const float b1 = __ldg(brs + o + 1);
            const size_t r0 = (size_t)(b * 128 + o) * L;
            const size_t x0 = (size_t)o * Tc;
            float* cc = acc2[mt][nt];
            if (full) {
                xout[r0 + t0 + t]         = cc[0] + b0 + xb[x0 + t0 + t + d];
                xout[r0 + L + t0 + t]     = cc[1] + b1 + xb[x0 + Tc + t0 + t + d];
                xout[r0 + t0 + t + 8]     = cc[2] + b0 + xb[x0 + t0 + t + 8 + d];
                xout[r0 + L + t0 + t + 8] = cc[3] + b1 + xb[x0 + Tc + t0 + t + 8 + d];
            } else {
                if (t0 + t < L) {
                    xout[r0 + t0 + t]     = cc[0] + b0 + xb[x0 + t0 + t + d];
                    xout[r0 + L + t0 + t] = cc[1] + b1 + xb[x0 + Tc + t0 + t + d];
                }
                if (t0 + t + 8 < L) {
                    xout[r0 + t0 + t + 8]     = cc[2] + b0 + xb[x0 + t0 + t + 8 + d];
                    xout[r0 + L + t0 + t + 8] = cc[3] + b1 + xb[x0 + Tc + t0 + t + 8 + d];
                }
            }
        }

    // ---- skip epilogue ----
    if (need_skip) {
        const bool wfull = full && (t0 >= sstart);
        #pragma unroll
        for (int mt = 0; mt < 2; ++mt)
            #pragma unroll
            for (int nt = 0; nt < 4; ++nt) {
                const int t = wm + mt * 16 + g;
                const int o = wn + nt * 8 + 2 * tg;
                const float b0 = __ldg(bsk + o);
                const float b1 = __ldg(bsk + o + 1);
                const size_t r0 = (size_t)(b * 128 + o) * SKIP_SIZE - sstart;
                float* cc = acc3[mt][nt];
                if (wfull) {
                    skip[r0 + t0 + t]                 = cc[0] + b0;
                    skip[r0 + SKIP_SIZE + t0 + t]     = cc[1] + b1;
                    skip[r0 + t0 + t + 8]             = cc[2] + b0;
                    skip[r0 + SKIP_SIZE + t0 + t + 8] = cc[3] + b1;
                } else {
                    const int tt0 = t0 + t, tt1 = t0 + t + 8;
                    if (tt0 >= sstart && tt0 < L) {
                        skip[r0 + tt0]             = cc[0] + b0;
                        skip[r0 + SKIP_SIZE + tt0] = cc[1] + b1;
                    }
                    if (tt1 >= sstart && tt1 < L) {
                        skip[r0 + tt1]             = cc[2] + b0;
                        skip[r0 + SKIP_SIZE + tt1] = cc[3] + b1;
                    }
                }
            }
    }

    CPWAIT(0);   // drain before CTA exit
}

// ---------------- host launcher ----------------
extern "C" void kernel_launch(void* const* d_in, const int* in_sizes, int n_in,
                              void* d_out, int out_size) {
    (void)in_sizes; (void)n_in; (void)out_size;

    const float* x     = (const float*)d_in[0];
    const float* wdil  = (const float*)d_in[1];
    const float* wres  = (const float*)d_in[2];
    const float* bres  = (const float*)d_in[3];
    const float* wskip = (const float*)d_in[4];
    const float* bskip = (const float*)d_in[5];
    float* out = (float*)d_out;

    float *bufA, *bufB;
    __half *w1, *w2;
    cudaGetSymbolAddress((void**)&bufA, g_bufA);
    cudaGetSymbolAddress((void**)&bufB, g_bufB);
    cudaGetSymbolAddress((void**)&w1,   g_w1h);
    cudaGetSymbolAddress((void**)&w2,   g_w2h);

    cudaFuncSetAttribute(wavenet_block, cudaFuncAttributeMaxDynamicSharedMemorySize, SMEM_BYTES);

    const int n1 = NBLK * W1BLK_H;
    prep_w1<<<(n1 + 255) / 256, 256>>>(wdil, w1, n1);
    prep_w2<<<(n1 + 255) / 256, 256>>>(wres, wskip, w2, n1);

    int Tc = T_START;
    const float* cur = x;
    float* nxt = bufA;
    for (int blk = 0; blk < NBLK; ++blk) {
        const int d = H_DIL[blk];
        const int L = Tc - d;
        dim3 grid((L + TN - 1) / TN, BATCH);
        wavenet_block<<<grid, NTHREADS, SMEM_BYTES>>>(
            cur, nxt,
            out + (size_t)blk * BATCH * RES_C * SKIP_SIZE,
            w1 + (size_t)blk * W1BLK_H,
            w2 + (size_t)blk * W2BLK_H,
            bres + blk * 128, bskip + blk * 128,
            Tc, d, L, L - SKIP_SIZE);
        cur = nxt;
        nxt = (nxt == bufA) ? bufB : bufA;
        Tc = L;
    }
}